// round 16
// baseline (speedup 1.0000x reference)
#include <cuda_runtime.h>
#include <cuda_bf16.h>

// Problem constants (fixed by setup_inputs):
//   encoder_output: (B=32, L_ENC=512, E=256) float32
//   durations:      (B=32, L_ENC=512) int32, values in [0, 8)
//   output:         (B=32, L_DEC=2048, E=256) float32
//
// out[b, d, :] = enc[b, l, :] where cs[l-1] <= d < cs[l]; 0 for d >= cs[511].

#define B_SZ    32
#define L_ENC   512
#define L_DEC   2048
#define E_DIM   256
#define E_VEC   (E_DIM / 4)            // 64 float4 per row
#define ROWS_PER_BLOCK 64              // decoder rows per block
#define BLOCKS_PER_BATCH (L_DEC / ROWS_PER_BLOCK)   // 32
#define ROWS_PER_GROUP 8               // 8 groups x 8 rows = 64
#define STAGE_BYTES (ROWS_PER_BLOCK * E_DIM * 4)    // 64 KB worst case

// ---------------------------------------------------------------------------
// Single fused kernel. Grid = 1024 blocks, 512 threads, 64KB dynamic smem.
// Per block (64 consecutive decoder rows of one batch):
//  1. in-block scan of batch durations -> per-enc-row [excl, incl)
//  2. s_map[64]: decoder row -> enc row (-1 pad)
//  3. run compaction (ballot/popc): s_runid[64], s_runsrc[nruns]
//  4. stage each DISTINCT enc row ONCE via LDG into smem (pad run = zeros)
//  5. gather: LDS.128 from staged rows (smem pipe, conflict-free) + STG.128
// Cuts L1tex warp-ops/block from 256 (R12) to ~164 while keeping all loads
// and stores batched/independent (no serial dedup chain).
// ---------------------------------------------------------------------------
__global__ void __launch_bounds__(512)
lr_fused_kernel(const float4* __restrict__ enc,
                const int*    __restrict__ dur,
                float4* __restrict__ out)
{
    extern __shared__ float4 s_stage[];      // 64 KB dynamic
    __shared__ int s_wsum[16];
    __shared__ int s_map[ROWS_PER_BLOCK];
    __shared__ int s_runid[ROWS_PER_BLOCK];
    __shared__ int s_runsrc[ROWS_PER_BLOCK];
    __shared__ int s_cnt[2];

    const int bid  = blockIdx.x;
    const int b    = bid >> 5;               // batch (32 blocks per batch)
    const int blk  = bid & 31;
    const int base = blk * ROWS_PER_BLOCK;   // decoder row base
    const int t    = threadIdx.x;
    const int wid  = t >> 5;
    const int lane = t & 31;

    // ---- 1. block-wide inclusive scan of this batch's 512 durations ----
    const int my_dur = dur[b * L_ENC + t];
    int v = my_dur;
    #pragma unroll
    for (int off = 1; off < 32; off <<= 1) {
        int u = __shfl_up_sync(0xffffffffu, v, off);
        if (lane >= off) v += u;
    }
    if (lane == 31) s_wsum[wid] = v;
    if (t < ROWS_PER_BLOCK) s_map[t] = -1;
    __syncthreads();

    if (wid == 0 && lane < 16) {
        int ws = s_wsum[lane];
        #pragma unroll
        for (int off = 1; off < 16; off <<= 1) {
            int u = __shfl_up_sync(0x0000ffffu, ws, off);
            if (lane >= off) ws += u;
        }
        s_wsum[lane] = ws - s_wsum[lane];
    }
    __syncthreads();

    const int incl = v + s_wsum[wid];        // inclusive cumsum at enc row t
    const int excl = incl - my_dur;

    // ---- 2. scatter: enc row t covers decoder rows [excl, incl) ----
    {
        int lo = excl > base ? excl : base;
        int hi = incl < base + ROWS_PER_BLOCK ? incl : base + ROWS_PER_BLOCK;
        for (int d = lo; d < hi; ++d)
            s_map[d - base] = t;
    }
    __syncthreads();

    // ---- 3. run compaction over the 64 map entries (warps 0 and 1) ----
    int my_incl = 0, my_new = 0;             // persist across barrier
    if (t < ROWS_PER_BLOCK) {
        const int prev = (t == 0) ? -2 : s_map[t - 1];
        my_new = (s_map[t] != prev) ? 1 : 0;
        const unsigned m = __ballot_sync(0xffffffffu, my_new);
        my_incl = __popc(m & (0xffffffffu >> (31 - lane)));   // inclusive cnt
        if (lane == 31) s_cnt[wid] = my_incl;                 // warp totals
    }
    __syncthreads();

    if (t < ROWS_PER_BLOCK) {
        const int rbase = (wid == 1) ? s_cnt[0] : 0;
        const int rid = rbase + my_incl - 1;
        s_runid[t] = rid;
        if (my_new) s_runsrc[rid] = s_map[t];
    }
    __syncthreads();

    // ---- 4. stage distinct rows compactly: LDG once per run ----
    const int nruns = s_cnt[0] + s_cnt[1];
    const float4* enc_b = enc + ((long)b * L_ENC) * E_VEC;
    for (int i = t; i < nruns * E_VEC; i += 512) {
        const int run = i >> 6;
        const int ln  = i & 63;
        const int s   = s_runsrc[run];
        float4 vv;
        if (s >= 0)
            vv = __ldg(enc_b + (long)s * E_VEC + ln);
        else
            vv = make_float4(0.f, 0.f, 0.f, 0.f);
        s_stage[i] = vv;
    }
    __syncthreads();

    // ---- 5. gather from smem, store 8 consecutive rows per group ----
    const int group = t >> 6;                // 0..7
    const int glane = t & 63;                // 0..63
    const int r0    = group * ROWS_PER_GROUP;

    int rid[ROWS_PER_GROUP];
    #pragma unroll
    for (int j = 0; j < ROWS_PER_GROUP; ++j)
        rid[j] = s_runid[r0 + j];            // broadcast LDS

    float4 vv[ROWS_PER_GROUP];
    #pragma unroll
    for (int j = 0; j < ROWS_PER_GROUP; ++j)
        vv[j] = s_stage[rid[j] * E_VEC + glane];   // LDS.128, conflict-free

    float4* out_rows = out + ((long)(b * L_DEC + base + r0)) * E_VEC;
    #pragma unroll
    for (int j = 0; j < ROWS_PER_GROUP; ++j)
        out_rows[(long)j * E_VEC + glane] = vv[j];
}

// ---------------------------------------------------------------------------
extern "C" void kernel_launch(void* const* d_in, const int* in_sizes, int n_in,
                              void* d_out, int out_size)
{
    const float* enc = (const float*)d_in[0];     // (B, L_ENC, E)
    const int*   dur = (const int*)d_in[1];       // (B, L_ENC) int32
    (void)in_sizes; (void)n_in; (void)out_size;

    cudaFuncSetAttribute(lr_fused_kernel,
                         cudaFuncAttributeMaxDynamicSharedMemorySize,
                         STAGE_BYTES);

    lr_fused_kernel<<<B_SZ * BLOCKS_PER_BATCH, 512, STAGE_BYTES>>>(
        (const float4*)enc, dur, (float4*)d_out);
}

// round 17
// speedup vs baseline: 1.2937x; 1.2937x over previous
#include <cuda_runtime.h>
#include <cuda_bf16.h>

// Problem constants (fixed by setup_inputs):
//   encoder_output: (B=32, L_ENC=512, E=256) float32
//   durations:      (B=32, L_ENC=512) int32, values in [0, 8)
//   output:         (B=32, L_DEC=2048, E=256) float32
//
// out[b, d, :] = enc[b, l, :] where cs[l-1] <= d < cs[l]; 0 for d >= cs[511].

#define B_SZ    32
#define L_ENC   512
#define L_DEC   2048
#define E_DIM   256
#define E_VEC   (E_DIM / 4)            // 64 float4 per row
#define ROWS_PER_BLOCK 64              // decoder rows per block
#define BLOCKS_PER_BATCH (L_DEC / ROWS_PER_BLOCK)   // 32
#define N_BLOCKS (B_SZ * BLOCKS_PER_BATCH)          // 1024
#define THREADS 256
#define N_GROUPS (THREADS / 64)        // 4 groups of 64 lanes
#define ROWS_PER_GROUP (ROWS_PER_BLOCK / N_GROUPS)  // 16 rows per group

// ---------------------------------------------------------------------------
// Single fused kernel. Grid = 1024 blocks x 256 threads = 262144 threads
// = 8192 warps -> SINGLE WAVE (capacity 9472): no wave-quantization loss,
// all 148 SMs covered with ~6.9 blocks each.
// Per block (64 consecutive decoder rows of one batch):
//  1. scan batch durations (2 per thread) -> cumsum
//  2. s_map[64]: decoder row -> enc row (-1 pad)
//  3. gather: 4 groups of 64 lanes copy 16 consecutive 1KB rows each
// ---------------------------------------------------------------------------
__global__ void __launch_bounds__(THREADS, 8)
lr_fused_kernel(const float4* __restrict__ enc,
                const int*    __restrict__ dur,
                float4* __restrict__ out)
{
    __shared__ int s_wsum[8];
    __shared__ int s_map[ROWS_PER_BLOCK];

    const int bid  = blockIdx.x;
    const int b    = bid >> 5;               // batch (32 blocks per batch)
    const int blk  = bid & 31;
    const int base = blk * ROWS_PER_BLOCK;   // decoder row base
    const int t    = threadIdx.x;            // 0..255
    const int wid  = t >> 5;                 // 0..7
    const int lane = t & 31;

    // ---- 1. scan: thread t owns enc rows 2t, 2t+1 ----
    const int d0 = dur[b * L_ENC + 2 * t];
    const int d1 = dur[b * L_ENC + 2 * t + 1];
    const int pair = d0 + d1;

    int v = pair;                             // inclusive scan of pair sums
    #pragma unroll
    for (int off = 1; off < 32; off <<= 1) {
        int u = __shfl_up_sync(0xffffffffu, v, off);
        if (lane >= off) v += u;
    }
    if (lane == 31) s_wsum[wid] = v;
    if (t < ROWS_PER_BLOCK) s_map[t] = -1;
    __syncthreads();

    if (wid == 0 && lane < 8) {
        int ws = s_wsum[lane];
        #pragma unroll
        for (int off = 1; off < 8; off <<= 1) {
            int u = __shfl_up_sync(0x000000ffu, ws, off);
            if (lane >= off) ws += u;
        }
        s_wsum[lane] = ws - s_wsum[lane];     // exclusive prefix of warp sums
    }
    __syncthreads();

    const int cs1   = v + s_wsum[wid];        // cumsum at enc row 2t+1
    const int cs0   = cs1 - d1;               // cumsum at enc row 2t
    const int excl0 = cs0 - d0;

    // ---- 2. scatter both intervals into the block's map ----
    {
        const int bend = base + ROWS_PER_BLOCK;
        int lo = excl0 > base ? excl0 : base;
        int hi = cs0 < bend ? cs0 : bend;
        for (int d = lo; d < hi; ++d) s_map[d - base] = 2 * t;
        lo = cs0 > base ? cs0 : base;
        hi = cs1 < bend ? cs1 : bend;
        for (int d = lo; d < hi; ++d) s_map[d - base] = 2 * t + 1;
    }
    __syncthreads();

    // ---- 3. gather: group g copies rows base + g*16 .. +15 ----
    const int group = t >> 6;                 // 0..3
    const int glane = t & 63;                 // 0..63
    const int r0    = group * ROWS_PER_GROUP;

    const float4* enc_b = enc + ((long)b * L_ENC) * E_VEC;
    float4* out_rows = out + ((long)(b * L_DEC + base + r0)) * E_VEC;

    #pragma unroll
    for (int j = 0; j < ROWS_PER_GROUP; ++j) {
        const int src = s_map[r0 + j];        // broadcast LDS
        float4 vv;
        if (src >= 0)
            vv = __ldg(enc_b + (long)src * E_VEC + glane);
        else
            vv = make_float4(0.f, 0.f, 0.f, 0.f);
        out_rows[(long)j * E_VEC + glane] = vv;
    }
}

// ---------------------------------------------------------------------------
extern "C" void kernel_launch(void* const* d_in, const int* in_sizes, int n_in,
                              void* d_out, int out_size)
{
    const float* enc = (const float*)d_in[0];     // (B, L_ENC, E)
    const int*   dur = (const int*)d_in[1];       // (B, L_ENC) int32
    (void)in_sizes; (void)n_in; (void)out_size;

    lr_fused_kernel<<<N_BLOCKS, THREADS>>>((const float4*)enc, dur,
                                           (float4*)d_out);
}